// round 6
// baseline (speedup 1.0000x reference)
#include <cuda_runtime.h>

#define B_ 512
#define L_ 100
#define E_ 50
#define D_ 512
#define DT 128
#define EP 64          // padded E rows for k3 weights
#define LP 112         // padded L rows for k5 weights
#define BLD ((size_t)B_ * L_ * D_)
#define NEGF -9000000000000000.0f

typedef unsigned long long ull;

// ---- scratch ----
__device__ float g_EDGE[(size_t)B_ * E_ * D_];     // edge feats (52 MB)
__device__ float g_ATTE2[(size_t)B_ * L_ * EP];    // att_edge  [b][l][e(pad64)]
__device__ float g_ATTN2[(size_t)B_ * E_ * LP];    // att_node  [b][e][l(pad112)]
__device__ float g_S[B_ * L_];                     // leaky(c0 + x.w_an)
__device__ float g_U[B_ * L_];                     // x.w_a2n
__device__ float g_wan[D_], g_wa2n[D_], g_w3e[D_];
__device__ float g_c0;

__device__ __forceinline__ float leaky(float x) { return x >= 0.f ? x : 0.2f * x; }

__device__ __forceinline__ ull fma2(ull a, ull b, ull c) {
    ull d;
    asm("fma.rn.f32x2 %0, %1, %2, %3;" : "=l"(d) : "l"(a), "l"(b), "l"(c));
    return d;
}
__device__ __forceinline__ ull add2(ull a, ull b) {
    ull d;
    asm("add.rn.f32x2 %0, %1, %2;" : "=l"(d) : "l"(a), "l"(b));
    return d;
}
__device__ __forceinline__ ull dup2(float x) {
    ull d;
    asm("mov.b64 %0, {%1, %1};" : "=l"(d) : "f"(x));
    return d;
}

// ---- K0: fold W2/W3 into vectors
__global__ void k0(const float* __restrict__ W2, const float* __restrict__ W3,
                   const float* __restrict__ ctx, const float* __restrict__ a,
                   const float* __restrict__ a2) {
    int d = threadIdx.x;      // 512
    int which = blockIdx.x;   // 4
    if (which < 3) {
        const float* M = (which == 2) ? W3 : W2;
        const float* vec = (which == 0) ? (a + D_) : (which == 1 ? a2 : (a2 + D_));
        float s = 0.f;
        for (int j = 0; j < D_; j++) s += M[(size_t)d * D_ + j] * vec[j];
        if (which == 0) g_wan[d] = s;
        else if (which == 1) g_wa2n[d] = s;
        else g_w3e[d] = s;
    } else {
        __shared__ float sh[512];
        sh[d] = ctx[d] * a[d];
        __syncthreads();
        for (int o = 256; o > 0; o >>= 1) { if (d < o) sh[d] += sh[d + o]; __syncthreads(); }
        if (d == 0) g_c0 = sh[0];
    }
}

// ---- K1: emb2 gather -> out3, dots from emb1 -> g_S, g_U
__global__ void k1(const int* __restrict__ inputs, const float* __restrict__ emb1,
                   const float* __restrict__ emb2, float* __restrict__ out3) {
    int bl = blockIdx.x;        // B*L
    int t = threadIdx.x;        // 128
    size_t nid = (size_t)inputs[bl];
    const float4* r1 = (const float4*)(emb1 + nid * D_);
    const float4* r2 = (const float4*)(emb2 + nid * D_);
    float4* o3 = (float4*)(out3 + (size_t)bl * D_);

    float4 v = r1[t];
    o3[t] = r2[t];
    float4 wa = ((const float4*)g_wan)[t];
    float4 wb = ((const float4*)g_wa2n)[t];
    float dan = v.x * wa.x + v.y * wa.y + v.z * wa.z + v.w * wa.w;
    float da2 = v.x * wb.x + v.y * wb.y + v.z * wb.z + v.w * wb.w;

    for (int off = 16; off; off >>= 1) {
        dan += __shfl_xor_sync(0xffffffffu, dan, off);
        da2 += __shfl_xor_sync(0xffffffffu, da2, off);
    }
    __shared__ float sA[4], sB[4];
    if ((t & 31) == 0) { sA[t >> 5] = dan; sB[t >> 5] = da2; }
    __syncthreads();
    if (t == 0) {
        float s = g_c0 + sA[0] + sA[1] + sA[2] + sA[3];
        g_S[bl] = leaky(s);
        g_U[bl] = sB[0] + sB[1] + sB[2] + sB[3];
    }
}

// ---- K2: att_edge softmax over l, layout ATTE2[b][l][e], e padded 64
__global__ void k2(const int* __restrict__ HT) {
    int b = blockIdx.x;
    __shared__ float s[L_];
    int t = threadIdx.x;   // 256
    if (t < L_) s[t] = g_S[b * L_ + t];
    float* op = g_ATTE2 + (size_t)b * L_ * EP;
    for (int idx = t; idx < L_ * (EP - E_); idx += 256) {
        int l = idx / (EP - E_), e = E_ + idx % (EP - E_);
        op[l * EP + e] = 0.f;
    }
    __syncthreads();
    int w = t >> 5, lane = t & 31;
    for (int e = w; e < E_; e += 8) {
        const int* m = HT + ((size_t)b * E_ + e) * L_;
        float vals[4];
        float mx = -3.4e38f;
        #pragma unroll
        for (int k = 0; k < 4; k++) {
            int l = lane + 32 * k;
            float v = -3.4e38f;
            if (l < L_) v = (m[l] > 0) ? s[l] : NEGF;
            vals[k] = v;
            mx = fmaxf(mx, v);
        }
        for (int off = 16; off; off >>= 1) mx = fmaxf(mx, __shfl_xor_sync(0xffffffffu, mx, off));
        float sum = 0.f;
        #pragma unroll
        for (int k = 0; k < 4; k++) {
            int l = lane + 32 * k;
            float ev = 0.f;
            if (l < L_) ev = expf(vals[k] - mx);
            vals[k] = ev;
            sum += ev;
        }
        for (int off = 16; off; off >>= 1) sum += __shfl_xor_sync(0xffffffffu, sum, off);
        float inv = 1.f / sum;
        #pragma unroll
        for (int k = 0; k < 4; k++) {
            int l = lane + 32 * k;
            if (l < L_) op[l * EP + e] = vals[k] * inv;
        }
    }
}

// ---- K3: edge[b,e,:] = sum_l attE[e,l] * emb1[inputs[b,l],:]
//      grid (B,4), block 128 = 16 jl x 8 eg. O=8 e-rows x J=8 cols per thread.
//      x rows read via LDG (L1-broadcast across warps); weights in smem only.
__global__ void __launch_bounds__(128) k3(const int* __restrict__ inputs,
                                          const float* __restrict__ emb1) {
    int b = blockIdx.x;
    int dt = blockIdx.y * DT;
    __shared__ float aw[L_][EP];          // 25.6 KB
    __shared__ int sidx[L_];
    int t = threadIdx.x;

    if (t < L_) sidx[t] = inputs[b * L_ + t];
    {
        const float4* src = (const float4*)(g_ATTE2 + (size_t)b * L_ * EP);
        for (int idx = t; idx < L_ * EP / 4; idx += 128) ((float4*)aw)[idx] = src[idx];
    }
    __syncthreads();

    int jl = t & 15, eg = t >> 4;
    int ja = jl * 4, jb = 64 + jl * 4;
    int e0 = eg * 8;
    ull acc[8][4];
    #pragma unroll
    for (int o = 0; o < 8; o++)
        #pragma unroll
        for (int j = 0; j < 4; j++) acc[o][j] = 0ULL;

    #pragma unroll 2
    for (int l = 0; l < L_; l++) {
        const float* xr = emb1 + (size_t)sidx[l] * D_ + dt;
        ulonglong2 xa = *(const ulonglong2*)(xr + ja);
        ulonglong2 xb = *(const ulonglong2*)(xr + jb);
        float4 wA = *(const float4*)&aw[l][e0];
        float4 wB = *(const float4*)&aw[l][e0 + 4];
        ull w[8] = {dup2(wA.x), dup2(wA.y), dup2(wA.z), dup2(wA.w),
                    dup2(wB.x), dup2(wB.y), dup2(wB.z), dup2(wB.w)};
        #pragma unroll
        for (int o = 0; o < 8; o++) {
            acc[o][0] = fma2(w[o], xa.x, acc[o][0]);
            acc[o][1] = fma2(w[o], xa.y, acc[o][1]);
            acc[o][2] = fma2(w[o], xb.x, acc[o][2]);
            acc[o][3] = fma2(w[o], xb.y, acc[o][3]);
        }
    }
    #pragma unroll
    for (int o = 0; o < 8; o++) {
        int e = e0 + o;
        if (e < E_) {
            float* p = g_EDGE + ((size_t)b * E_ + e) * D_ + dt;
            *(ulonglong2*)(p + ja) = make_ulonglong2(acc[o][0], acc[o][1]);
            *(ulonglong2*)(p + jb) = make_ulonglong2(acc[o][2], acc[o][3]);
        }
    }
}

// ---- K4: v[b,e] = edge.w3e; att_node softmax over e, layout ATTN2[b][e][l], l padded 112
__global__ void k4(const int* __restrict__ HT) {
    int b = blockIdx.x;
    int t = threadIdx.x;   // 256
    __shared__ float vsh[E_];
    __shared__ float ush[L_];
    __shared__ float4 wsh[D_ / 4];
    int w = t >> 5, lane = t & 31;
    for (int i = t; i < D_ / 4; i += 256) wsh[i] = ((const float4*)g_w3e)[i];
    if (t < L_) ush[t] = g_U[b * L_ + t];
    float* op = g_ATTN2 + (size_t)b * E_ * LP;
    for (int idx = t; idx < E_ * (LP - L_); idx += 256) {
        int e = idx / (LP - L_), l = L_ + idx % (LP - L_);
        op[e * LP + l] = 0.f;
    }
    __syncthreads();
    for (int e = w; e < E_; e += 8) {
        const float4* er = (const float4*)(g_EDGE + ((size_t)b * E_ + e) * D_);
        float d = 0.f;
        #pragma unroll
        for (int i = 0; i < 4; i++) {
            float4 ev = er[lane + 32 * i];
            float4 wv = wsh[lane + 32 * i];
            d += ev.x * wv.x + ev.y * wv.y + ev.z * wv.z + ev.w * wv.w;
        }
        for (int off = 16; off; off >>= 1) d += __shfl_xor_sync(0xffffffffu, d, off);
        if (lane == 0) vsh[e] = d;
    }
    __syncthreads();

    if (t < L_) {
        int l = t;
        float u = ush[l];
        float vals[E_];
        float mx = -3.4e38f;
        #pragma unroll
        for (int e = 0; e < E_; e++) {
            float s2 = leaky(u + vsh[e]);
            float val = (HT[((size_t)b * E_ + e) * L_ + l] > 0) ? s2 : NEGF;
            vals[e] = val;
            mx = fmaxf(mx, val);
        }
        float sum = 0.f;
        #pragma unroll
        for (int e = 0; e < E_; e++) { vals[e] = expf(vals[e] - mx); sum += vals[e]; }
        float inv = 1.f / sum;
        #pragma unroll
        for (int e = 0; e < E_; e++) op[e * LP + l] = vals[e] * inv;
    }
}

// ---- K5: node[b,l,:] = sum_e attN[e,l] * edge[e,:] + x; write out twice.
//      grid (B,4), block 224 = 16 jl x 14 lg. O=8 l-rows x J=8 cols per thread.
//      edge rows via LDG (L1 broadcast); weights in smem.
__global__ void __launch_bounds__(224) k5(const int* __restrict__ inputs,
                                          const float* __restrict__ emb1,
                                          float* __restrict__ out) {
    int b = blockIdx.x;
    int dt = blockIdx.y * DT;
    __shared__ float an[E_][LP];          // 22.4 KB
    __shared__ int sidx[L_];
    int t = threadIdx.x;

    if (t < L_) sidx[t] = inputs[b * L_ + t];
    {
        const float4* src = (const float4*)(g_ATTN2 + (size_t)b * E_ * LP);
        for (int idx = t; idx < E_ * LP / 4; idx += 224) ((float4*)an)[idx] = src[idx];
    }
    __syncthreads();

    int jl = t & 15, lg = t >> 4;   // lg 0..13
    int ja = jl * 4, jb = 64 + jl * 4;
    int l0 = lg * 8;
    ull acc[8][4];
    #pragma unroll
    for (int o = 0; o < 8; o++)
        #pragma unroll
        for (int j = 0; j < 4; j++) acc[o][j] = 0ULL;

    const float* ebase = g_EDGE + (size_t)b * E_ * D_ + dt;
    #pragma unroll 2
    for (int e = 0; e < E_; e++) {
        const float* er = ebase + (size_t)e * D_;
        ulonglong2 xa = *(const ulonglong2*)(er + ja);
        ulonglong2 xb = *(const ulonglong2*)(er + jb);
        float4 wA = *(const float4*)&an[e][l0];
        float4 wB = *(const float4*)&an[e][l0 + 4];
        ull w[8] = {dup2(wA.x), dup2(wA.y), dup2(wA.z), dup2(wA.w),
                    dup2(wB.x), dup2(wB.y), dup2(wB.z), dup2(wB.w)};
        #pragma unroll
        for (int o = 0; o < 8; o++) {
            acc[o][0] = fma2(w[o], xa.x, acc[o][0]);
            acc[o][1] = fma2(w[o], xa.y, acc[o][1]);
            acc[o][2] = fma2(w[o], xb.x, acc[o][2]);
            acc[o][3] = fma2(w[o], xb.y, acc[o][3]);
        }
    }
    #pragma unroll
    for (int o = 0; o < 8; o++) {
        int l = l0 + o;
        if (l < L_) {
            size_t off = ((size_t)b * L_ + l) * D_ + dt;
            const float* xr = emb1 + (size_t)sidx[l] * D_ + dt;
            ulonglong2 xva = *(const ulonglong2*)(xr + ja);
            ulonglong2 xvb = *(const ulonglong2*)(xr + jb);
            ulonglong2 oa = make_ulonglong2(add2(acc[o][0], xva.x), add2(acc[o][1], xva.y));
            ulonglong2 ob = make_ulonglong2(add2(acc[o][2], xvb.x), add2(acc[o][3], xvb.y));
            *(ulonglong2*)(out + off + ja) = oa;
            *(ulonglong2*)(out + BLD + off + ja) = oa;
            *(ulonglong2*)(out + off + jb) = ob;
            *(ulonglong2*)(out + BLD + off + jb) = ob;
        }
    }
}

extern "C" void kernel_launch(void* const* d_in, const int* in_sizes, int n_in,
                              void* d_out, int out_size) {
    const int*   inputs = (const int*)d_in[0];
    const int*   HT     = (const int*)d_in[1];
    const float* emb1   = (const float*)d_in[4];
    const float* emb2   = (const float*)d_in[5];
    const float* W2     = (const float*)d_in[6];
    const float* W3     = (const float*)d_in[7];
    const float* ctx    = (const float*)d_in[8];
    const float* a      = (const float*)d_in[9];
    const float* a2     = (const float*)d_in[10];
    float* out = (float*)d_out;

    k0<<<4, 512>>>(W2, W3, ctx, a, a2);
    k1<<<B_ * L_, 128>>>(inputs, emb1, emb2, out + 2 * BLD);
    k2<<<B_, 256>>>(HT);
    k3<<<dim3(B_, 4), 128>>>(inputs, emb1);
    k4<<<B_, 256>>>(HT);
    k5<<<dim3(B_, 4), 224>>>(inputs, emb1, out);
}

// round 7
// speedup vs baseline: 1.5387x; 1.5387x over previous
#include <cuda_runtime.h>

#define B_ 512
#define L_ 100
#define E_ 50
#define D_ 512
#define DT 128
#define BLD ((size_t)B_ * L_ * D_)
#define NEGF -9000000000000000.0f

typedef unsigned long long ull;

// ---- scratch ----
__device__ float g_EDGE[(size_t)B_ * E_ * D_];     // edge feats (52 MB)
__device__ float2 g_ATTEP[(size_t)B_ * L_ * 28];   // att_edge, e-pair packed [b][l][pair]
__device__ float2 g_ATTNP[(size_t)B_ * E_ * 52];   // att_node, l-pair packed [b][e][pair]
__device__ float g_S[B_ * L_];                     // leaky(c0 + x.w_an)
__device__ float g_U[B_ * L_];                     // x.w_a2n
__device__ float g_wan[D_], g_wa2n[D_], g_w3e[D_];
__device__ float g_c0;

__device__ __forceinline__ float leaky(float x) { return x >= 0.f ? x : 0.2f * x; }

__device__ __forceinline__ ull fma2(ull a, ull b, ull c) {
    ull d;
    asm("fma.rn.f32x2 %0, %1, %2, %3;" : "=l"(d) : "l"(a), "l"(b), "l"(c));
    return d;
}
__device__ __forceinline__ ull dup2(float x) {
    ull d;
    asm("mov.b64 %0, {%1, %1};" : "=l"(d) : "f"(x));
    return d;
}
__device__ __forceinline__ float lo32(ull v) { return ((float2*)&v)->x; }
__device__ __forceinline__ float hi32(ull v) { return ((float2*)&v)->y; }

// ---- K0: fold W2/W3 into vectors
__global__ void k0(const float* __restrict__ W2, const float* __restrict__ W3,
                   const float* __restrict__ ctx, const float* __restrict__ a,
                   const float* __restrict__ a2) {
    int d = threadIdx.x;      // 512
    int which = blockIdx.x;   // 4
    if (which < 3) {
        const float* M = (which == 2) ? W3 : W2;
        const float* vec = (which == 0) ? (a + D_) : (which == 1 ? a2 : (a2 + D_));
        float s = 0.f;
        for (int j = 0; j < D_; j++) s += M[(size_t)d * D_ + j] * vec[j];
        if (which == 0) g_wan[d] = s;
        else if (which == 1) g_wa2n[d] = s;
        else g_w3e[d] = s;
    } else {
        __shared__ float sh[512];
        sh[d] = ctx[d] * a[d];
        __syncthreads();
        for (int o = 256; o > 0; o >>= 1) { if (d < o) sh[d] += sh[d + o]; __syncthreads(); }
        if (d == 0) g_c0 = sh[0];
    }
}

// ---- K1: emb2 gather -> out3, dots from emb1 -> g_S, g_U (no g_X store)
__global__ void k1(const int* __restrict__ inputs, const float* __restrict__ emb1,
                   const float* __restrict__ emb2, float* __restrict__ out3) {
    int bl = blockIdx.x;        // B*L
    int t = threadIdx.x;        // 128
    size_t nid = (size_t)inputs[bl];
    const float4* r1 = (const float4*)(emb1 + nid * D_);
    const float4* r2 = (const float4*)(emb2 + nid * D_);
    float4* o3 = (float4*)(out3 + (size_t)bl * D_);

    float4 v = r1[t];
    o3[t] = r2[t];
    float4 wa = ((const float4*)g_wan)[t];
    float4 wb = ((const float4*)g_wa2n)[t];
    float dan = v.x * wa.x + v.y * wa.y + v.z * wa.z + v.w * wa.w;
    float da2 = v.x * wb.x + v.y * wb.y + v.z * wb.z + v.w * wb.w;

    for (int off = 16; off; off >>= 1) {
        dan += __shfl_xor_sync(0xffffffffu, dan, off);
        da2 += __shfl_xor_sync(0xffffffffu, da2, off);
    }
    __shared__ float sA[4], sB[4];
    if ((t & 31) == 0) { sA[t >> 5] = dan; sB[t >> 5] = da2; }
    __syncthreads();
    if (t == 0) {
        float s = g_c0 + sA[0] + sA[1] + sA[2] + sA[3];
        g_S[bl] = leaky(s);
        g_U[bl] = sB[0] + sB[1] + sB[2] + sB[3];
    }
}

// ---- K2: att_edge softmax over l, written e-pair-packed: ATTEP[b][l][e>>1].{x,y}
__global__ void k2(const int* __restrict__ HT) {
    int b = blockIdx.x;
    __shared__ float s[L_];
    int t = threadIdx.x;   // 256
    if (t < L_) s[t] = g_S[b * L_ + t];
    for (int idx = t; idx < L_ * 3; idx += 256) {
        int l = idx / 3, p = 25 + idx % 3;
        g_ATTEP[(size_t)b * L_ * 28 + l * 28 + p] = make_float2(0.f, 0.f);
    }
    __syncthreads();
    float* op = (float*)(g_ATTEP + (size_t)b * L_ * 28);
    int w = t >> 5, lane = t & 31;
    for (int e = w; e < E_; e += 8) {
        const int* m = HT + ((size_t)b * E_ + e) * L_;
        float vals[4];
        float mx = -3.4e38f;
        #pragma unroll
        for (int k = 0; k < 4; k++) {
            int l = lane + 32 * k;
            float v = -3.4e38f;
            if (l < L_) v = (m[l] > 0) ? s[l] : NEGF;
            vals[k] = v;
            mx = fmaxf(mx, v);
        }
        for (int off = 16; off; off >>= 1) mx = fmaxf(mx, __shfl_xor_sync(0xffffffffu, mx, off));
        float sum = 0.f;
        #pragma unroll
        for (int k = 0; k < 4; k++) {
            int l = lane + 32 * k;
            float ev = 0.f;
            if (l < L_) ev = expf(vals[k] - mx);
            vals[k] = ev;
            sum += ev;
        }
        for (int off = 16; off; off >>= 1) sum += __shfl_xor_sync(0xffffffffu, sum, off);
        float inv = 1.f / sum;
        #pragma unroll
        for (int k = 0; k < 4; k++) {
            int l = lane + 32 * k;
            if (l < L_) op[(l * 28 + (e >> 1)) * 2 + (e & 1)] = vals[k] * inv;
        }
    }
}

// ---- K3: edge[b,e,:] = sum_l attE[b,e,l] * emb1[inputs[b,l],:]
//      grid (B,4), block 448 = 14 warps x 2 e-pairs. (R4-proven tile; x gathered
//      directly from emb1 into smem — g_X eliminated.)
__global__ void __launch_bounds__(448, 3) k3(const int* __restrict__ inputs,
                                             const float* __restrict__ emb1) {
    int b = blockIdx.x;
    int dt = blockIdx.y * DT;
    __shared__ float xs[L_][DT];          // 51.2 KB
    __shared__ float2 awp[L_][28];        // 22.4 KB
    __shared__ int sidx[L_];
    int t = threadIdx.x;

    if (t < L_) sidx[t] = inputs[b * L_ + t];
    __syncthreads();
    for (int idx = t; idx < L_ * (DT / 4); idx += 448) {
        int l = idx >> 5, q = idx & 31;
        ((float4*)xs[l])[q] = *(const float4*)(emb1 + (size_t)sidx[l] * D_ + dt + q * 4);
    }
    {
        const float4* src = (const float4*)(g_ATTEP + (size_t)b * L_ * 28);
        float4* dst = (float4*)&awp[0][0];
        for (int idx = t; idx < L_ * 28 / 2; idx += 448) dst[idx] = src[idx];
    }
    __syncthreads();

    int lane = t & 31, w = t >> 5;   // w 0..13
    int j0 = lane * 4;
    int p0 = 2 * w;                  // pairs p0, p0+1
    ull acc[2][4];
    #pragma unroll
    for (int k = 0; k < 2; k++)
        #pragma unroll
        for (int j = 0; j < 4; j++) acc[k][j] = 0ULL;

    #pragma unroll 2
    for (int l = 0; l < L_; l++) {
        float4 xv = *(const float4*)&xs[l][j0];
        ull xx[4] = {dup2(xv.x), dup2(xv.y), dup2(xv.z), dup2(xv.w)};
        ulonglong2 wp = *(const ulonglong2*)&awp[l][p0];
        #pragma unroll
        for (int j = 0; j < 4; j++) {
            acc[0][j] = fma2(wp.x, xx[j], acc[0][j]);
            acc[1][j] = fma2(wp.y, xx[j], acc[1][j]);
        }
    }
    #pragma unroll
    for (int k = 0; k < 2; k++) {
        int p = p0 + k;
        if (p < 25) {
            int e0 = 2 * p;
            float4 o0 = make_float4(lo32(acc[k][0]), lo32(acc[k][1]), lo32(acc[k][2]), lo32(acc[k][3]));
            float4 o1 = make_float4(hi32(acc[k][0]), hi32(acc[k][1]), hi32(acc[k][2]), hi32(acc[k][3]));
            *(float4*)(g_EDGE + ((size_t)b * E_ + e0) * D_ + dt + j0) = o0;
            *(float4*)(g_EDGE + ((size_t)b * E_ + e0 + 1) * D_ + dt + j0) = o1;
        }
    }
}

// ---- K4: v[b,e] = edge.w3e; att_node softmax over e, written l-pair-packed
__global__ void k4(const int* __restrict__ HT) {
    int b = blockIdx.x;
    int t = threadIdx.x;   // 256
    __shared__ float vsh[E_];
    __shared__ float ush[L_];
    __shared__ float4 wsh[D_ / 4];
    int w = t >> 5, lane = t & 31;
    for (int i = t; i < D_ / 4; i += 256) wsh[i] = ((const float4*)g_w3e)[i];
    if (t < L_) ush[t] = g_U[b * L_ + t];
    for (int idx = t; idx < E_ * 2; idx += 256) {
        int e = idx >> 1, p = 50 + (idx & 1);
        g_ATTNP[(size_t)b * E_ * 52 + e * 52 + p] = make_float2(0.f, 0.f);
    }
    __syncthreads();
    for (int e = w; e < E_; e += 8) {
        const float4* er = (const float4*)(g_EDGE + ((size_t)b * E_ + e) * D_);
        float d = 0.f;
        #pragma unroll
        for (int i = 0; i < 4; i++) {
            float4 ev = er[lane + 32 * i];
            float4 wv = wsh[lane + 32 * i];
            d += ev.x * wv.x + ev.y * wv.y + ev.z * wv.z + ev.w * wv.w;
        }
        for (int off = 16; off; off >>= 1) d += __shfl_xor_sync(0xffffffffu, d, off);
        if (lane == 0) vsh[e] = d;
    }
    __syncthreads();

    if (t < L_) {
        int l = t;
        float u = ush[l];
        float vals[E_];
        float mx = -3.4e38f;
        #pragma unroll
        for (int e = 0; e < E_; e++) {
            float s2 = leaky(u + vsh[e]);
            float val = (HT[((size_t)b * E_ + e) * L_ + l] > 0) ? s2 : NEGF;
            vals[e] = val;
            mx = fmaxf(mx, val);
        }
        float sum = 0.f;
        #pragma unroll
        for (int e = 0; e < E_; e++) { vals[e] = expf(vals[e] - mx); sum += vals[e]; }
        float inv = 1.f / sum;
        float* op = (float*)(g_ATTNP + (size_t)b * E_ * 52);
        #pragma unroll
        for (int e = 0; e < E_; e++) op[(e * 52 + (l >> 1)) * 2 + (l & 1)] = vals[e] * inv;
    }
}

// ---- K5: node = att_node @ edge + x; write out twice.
//      grid (B,4), block 416 = 13 warps x 4 l-pairs (R4-proven tile; residual x
//      read directly from emb1 — g_X eliminated).
__global__ void __launch_bounds__(416, 2) k5(const int* __restrict__ inputs,
                                             const float* __restrict__ emb1,
                                             float* __restrict__ out) {
    int b = blockIdx.x;
    int dt = blockIdx.y * DT;
    __shared__ float es[E_][DT];          // 25.6 KB
    __shared__ float2 anp[E_][52];        // 20.8 KB
    __shared__ int sidx[L_];
    int t = threadIdx.x;

    if (t < L_) sidx[t] = inputs[b * L_ + t];
    for (int idx = t; idx < E_ * (DT / 4); idx += 416) {
        int e = idx >> 5, q = idx & 31;
        ((float4*)es[e])[q] = *(const float4*)(g_EDGE + ((size_t)b * E_ + e) * D_ + dt + q * 4);
    }
    {
        const float4* src = (const float4*)(g_ATTNP + (size_t)b * E_ * 52);
        float4* dst = (float4*)&anp[0][0];
        for (int idx = t; idx < E_ * 52 / 2; idx += 416) dst[idx] = src[idx];
    }
    __syncthreads();

    int lane = t & 31, w = t >> 5;   // w 0..12
    int j0 = lane * 4;
    int p0 = 4 * w;                  // pairs p0..p0+3
    ull acc[4][4];
    #pragma unroll
    for (int k = 0; k < 4; k++)
        #pragma unroll
        for (int j = 0; j < 4; j++) acc[k][j] = 0ULL;

    #pragma unroll 2
    for (int e = 0; e < E_; e++) {
        float4 xv = *(const float4*)&es[e][j0];
        ull xx[4] = {dup2(xv.x), dup2(xv.y), dup2(xv.z), dup2(xv.w)};
        ulonglong2 wa = *(const ulonglong2*)&anp[e][p0];
        ulonglong2 wb = *(const ulonglong2*)&anp[e][p0 + 2];
        #pragma unroll
        for (int j = 0; j < 4; j++) {
            acc[0][j] = fma2(wa.x, xx[j], acc[0][j]);
            acc[1][j] = fma2(wa.y, xx[j], acc[1][j]);
            acc[2][j] = fma2(wb.x, xx[j], acc[2][j]);
            acc[3][j] = fma2(wb.y, xx[j], acc[3][j]);
        }
    }
    #pragma unroll
    for (int k = 0; k < 4; k++) {
        int p = p0 + k;
        if (p < 50) {
            int l0 = 2 * p;
            size_t off0 = ((size_t)b * L_ + l0) * D_ + dt + j0;
            size_t off1 = off0 + D_;
            const float* x0p = emb1 + (size_t)sidx[l0] * D_ + dt + j0;
            const float* x1p = emb1 + (size_t)sidx[l0 + 1] * D_ + dt + j0;
            float4 x0 = *(const float4*)x0p;
            float4 x1 = *(const float4*)x1p;
            float4 o0 = make_float4(lo32(acc[k][0]) + x0.x, lo32(acc[k][1]) + x0.y,
                                    lo32(acc[k][2]) + x0.z, lo32(acc[k][3]) + x0.w);
            float4 o1 = make_float4(hi32(acc[k][0]) + x1.x, hi32(acc[k][1]) + x1.y,
                                    hi32(acc[k][2]) + x1.z, hi32(acc[k][3]) + x1.w);
            *(float4*)(out + off0) = o0;
            *(float4*)(out + BLD + off0) = o0;
            *(float4*)(out + off1) = o1;
            *(float4*)(out + BLD + off1) = o1;
        }
    }
}

extern "C" void kernel_launch(void* const* d_in, const int* in_sizes, int n_in,
                              void* d_out, int out_size) {
    const int*   inputs = (const int*)d_in[0];
    const int*   HT     = (const int*)d_in[1];
    const float* emb1   = (const float*)d_in[4];
    const float* emb2   = (const float*)d_in[5];
    const float* W2     = (const float*)d_in[6];
    const float* W3     = (const float*)d_in[7];
    const float* ctx    = (const float*)d_in[8];
    const float* a      = (const float*)d_in[9];
    const float* a2     = (const float*)d_in[10];
    float* out = (float*)d_out;

    k0<<<4, 512>>>(W2, W3, ctx, a, a2);
    k1<<<B_ * L_, 128>>>(inputs, emb1, emb2, out + 2 * BLD);
    k2<<<B_, 256>>>(HT);
    k3<<<dim3(B_, 4), 448>>>(inputs, emb1);
    k4<<<B_, 256>>>(HT);
    k5<<<dim3(B_, 4), 416>>>(inputs, emb1, out);
}

// round 8
// speedup vs baseline: 1.5529x; 1.0092x over previous
#include <cuda_runtime.h>

#define B_ 512
#define L_ 100
#define E_ 50
#define D_ 512
#define DT 128
#define BLD ((size_t)B_ * L_ * D_)
#define NEGF -9000000000000000.0f

typedef unsigned long long ull;

// ---- scratch ----
__device__ float g_EDGE[(size_t)B_ * E_ * D_];     // edge feats (52 MB)
__device__ float2 g_ATTEP[(size_t)B_ * L_ * 28];   // att_edge, e-pair packed [b][l][pair]
__device__ float2 g_ATTNP[(size_t)B_ * E_ * 52];   // att_node, l-pair packed [b][e][pair]
__device__ float g_S[B_ * L_];                     // leaky(c0 + x.w_an)
__device__ float g_U[B_ * L_];                     // x.w_a2n
__device__ float g_wan[D_], g_wa2n[D_], g_w3e[D_];
__device__ float g_c0;

__device__ __forceinline__ float leaky(float x) { return x >= 0.f ? x : 0.2f * x; }

__device__ __forceinline__ ull fma2(ull a, ull b, ull c) {
    ull d;
    asm("fma.rn.f32x2 %0, %1, %2, %3;" : "=l"(d) : "l"(a), "l"(b), "l"(c));
    return d;
}
__device__ __forceinline__ ull dup2(float x) {
    ull d;
    asm("mov.b64 %0, {%1, %1};" : "=l"(d) : "f"(x));
    return d;
}
__device__ __forceinline__ float lo32(ull v) { return ((float2*)&v)->x; }
__device__ __forceinline__ float hi32(ull v) { return ((float2*)&v)->y; }

// ---- K0: fold W2/W3 into vectors
__global__ void k0(const float* __restrict__ W2, const float* __restrict__ W3,
                   const float* __restrict__ ctx, const float* __restrict__ a,
                   const float* __restrict__ a2) {
    int d = threadIdx.x;      // 512
    int which = blockIdx.x;   // 4
    if (which < 3) {
        const float* M = (which == 2) ? W3 : W2;
        const float* vec = (which == 0) ? (a + D_) : (which == 1 ? a2 : (a2 + D_));
        float s = 0.f;
        for (int j = 0; j < D_; j++) s += M[(size_t)d * D_ + j] * vec[j];
        if (which == 0) g_wan[d] = s;
        else if (which == 1) g_wa2n[d] = s;
        else g_w3e[d] = s;
    } else {
        __shared__ float sh[512];
        sh[d] = ctx[d] * a[d];
        __syncthreads();
        for (int o = 256; o > 0; o >>= 1) { if (d < o) sh[d] += sh[d + o]; __syncthreads(); }
        if (d == 0) g_c0 = sh[0];
    }
}

// ---- K1: emb2 gather -> out3, dots from emb1 -> g_S, g_U
__global__ void k1(const int* __restrict__ inputs, const float* __restrict__ emb1,
                   const float* __restrict__ emb2, float* __restrict__ out3) {
    int bl = blockIdx.x;        // B*L
    int t = threadIdx.x;        // 128
    size_t nid = (size_t)inputs[bl];
    const float4* r1 = (const float4*)(emb1 + nid * D_);
    const float4* r2 = (const float4*)(emb2 + nid * D_);
    float4* o3 = (float4*)(out3 + (size_t)bl * D_);

    float4 v = r1[t];
    o3[t] = r2[t];
    float4 wa = ((const float4*)g_wan)[t];
    float4 wb = ((const float4*)g_wa2n)[t];
    float dan = v.x * wa.x + v.y * wa.y + v.z * wa.z + v.w * wa.w;
    float da2 = v.x * wb.x + v.y * wb.y + v.z * wb.z + v.w * wb.w;

    for (int off = 16; off; off >>= 1) {
        dan += __shfl_xor_sync(0xffffffffu, dan, off);
        da2 += __shfl_xor_sync(0xffffffffu, da2, off);
    }
    __shared__ float sA[4], sB[4];
    if ((t & 31) == 0) { sA[t >> 5] = dan; sB[t >> 5] = da2; }
    __syncthreads();
    if (t == 0) {
        float s = g_c0 + sA[0] + sA[1] + sA[2] + sA[3];
        g_S[bl] = leaky(s);
        g_U[bl] = sB[0] + sB[1] + sB[2] + sB[3];
    }
}

// ---- K2: att_edge softmax over l, written e-pair-packed: ATTEP[b][l][e>>1].{x,y}
__global__ void k2(const int* __restrict__ HT) {
    int b = blockIdx.x;
    __shared__ float s[L_];
    int t = threadIdx.x;   // 256
    if (t < L_) s[t] = g_S[b * L_ + t];
    for (int idx = t; idx < L_ * 3; idx += 256) {
        int l = idx / 3, p = 25 + idx % 3;
        g_ATTEP[(size_t)b * L_ * 28 + l * 28 + p] = make_float2(0.f, 0.f);
    }
    __syncthreads();
    float* op = (float*)(g_ATTEP + (size_t)b * L_ * 28);
    int w = t >> 5, lane = t & 31;
    for (int e = w; e < E_; e += 8) {
        const int* m = HT + ((size_t)b * E_ + e) * L_;
        float vals[4];
        float mx = -3.4e38f;
        #pragma unroll
        for (int k = 0; k < 4; k++) {
            int l = lane + 32 * k;
            float v = -3.4e38f;
            if (l < L_) v = (m[l] > 0) ? s[l] : NEGF;
            vals[k] = v;
            mx = fmaxf(mx, v);
        }
        for (int off = 16; off; off >>= 1) mx = fmaxf(mx, __shfl_xor_sync(0xffffffffu, mx, off));
        float sum = 0.f;
        #pragma unroll
        for (int k = 0; k < 4; k++) {
            int l = lane + 32 * k;
            float ev = 0.f;
            if (l < L_) ev = expf(vals[k] - mx);
            vals[k] = ev;
            sum += ev;
        }
        for (int off = 16; off; off >>= 1) sum += __shfl_xor_sync(0xffffffffu, sum, off);
        float inv = 1.f / sum;
        #pragma unroll
        for (int k = 0; k < 4; k++) {
            int l = lane + 32 * k;
            if (l < L_) op[(l * 28 + (e >> 1)) * 2 + (e & 1)] = vals[k] * inv;
        }
    }
}

// ---- K3: edge[b,e,:] = sum_l attE[b,e,l] * emb1[inputs[b,l],:]
//      grid (B,4), block 448 = 14 warps = 7 pair-groups x 2 j-halves.
//      Per thread: P=4 e-pairs (8 e-rows) x J=2 cols. Weight LDS is warp-uniform
//      (broadcast, ~free); x LDS.64 per lane.
__global__ void __launch_bounds__(448, 3) k3(const int* __restrict__ inputs,
                                             const float* __restrict__ emb1) {
    int b = blockIdx.x;
    int dt = blockIdx.y * DT;
    __shared__ float xs[L_][DT];          // 51.2 KB
    __shared__ float2 awp[L_][28];        // 22.4 KB
    __shared__ int sidx[L_];
    int t = threadIdx.x;

    if (t < L_) sidx[t] = inputs[b * L_ + t];
    __syncthreads();
    for (int idx = t; idx < L_ * (DT / 4); idx += 448) {
        int l = idx >> 5, q = idx & 31;
        ((float4*)xs[l])[q] = *(const float4*)(emb1 + (size_t)sidx[l] * D_ + dt + q * 4);
    }
    {
        const float4* src = (const float4*)(g_ATTEP + (size_t)b * L_ * 28);
        float4* dst = (float4*)&awp[0][0];
        for (int idx = t; idx < L_ * 28 / 2; idx += 448) dst[idx] = src[idx];
    }
    __syncthreads();

    int lane = t & 31, w = t >> 5;   // w 0..13
    int pg = w % 7;                  // pair group: pairs 4pg..4pg+3
    int jh = w / 7;                  // j half
    int j0 = jh * 64 + lane * 2;
    int p0 = 4 * pg;
    ull acc[4][2];
    #pragma unroll
    for (int k = 0; k < 4; k++) { acc[k][0] = 0ULL; acc[k][1] = 0ULL; }

    #pragma unroll 2
    for (int l = 0; l < L_; l++) {
        float2 xv = *(const float2*)&xs[l][j0];
        ull xx0 = dup2(xv.x), xx1 = dup2(xv.y);
        ulonglong2 wA = *(const ulonglong2*)&awp[l][p0];       // pairs p0, p0+1
        ulonglong2 wB = *(const ulonglong2*)&awp[l][p0 + 2];   // pairs p0+2, p0+3
        acc[0][0] = fma2(wA.x, xx0, acc[0][0]);
        acc[0][1] = fma2(wA.x, xx1, acc[0][1]);
        acc[1][0] = fma2(wA.y, xx0, acc[1][0]);
        acc[1][1] = fma2(wA.y, xx1, acc[1][1]);
        acc[2][0] = fma2(wB.x, xx0, acc[2][0]);
        acc[2][1] = fma2(wB.x, xx1, acc[2][1]);
        acc[3][0] = fma2(wB.y, xx0, acc[3][0]);
        acc[3][1] = fma2(wB.y, xx1, acc[3][1]);
    }
    #pragma unroll
    for (int k = 0; k < 4; k++) {
        int p = p0 + k;
        if (p < 25) {
            int e0 = 2 * p;
            float2 o0 = make_float2(lo32(acc[k][0]), lo32(acc[k][1]));
            float2 o1 = make_float2(hi32(acc[k][0]), hi32(acc[k][1]));
            *(float2*)(g_EDGE + ((size_t)b * E_ + e0) * D_ + dt + j0) = o0;
            *(float2*)(g_EDGE + ((size_t)b * E_ + e0 + 1) * D_ + dt + j0) = o1;
        }
    }
}

// ---- K4: v[b,e] = edge.w3e; att_node softmax over e, written l-pair-packed
__global__ void k4(const int* __restrict__ HT) {
    int b = blockIdx.x;
    int t = threadIdx.x;   // 256
    __shared__ float vsh[E_];
    __shared__ float ush[L_];
    __shared__ float4 wsh[D_ / 4];
    int w = t >> 5, lane = t & 31;
    for (int i = t; i < D_ / 4; i += 256) wsh[i] = ((const float4*)g_w3e)[i];
    if (t < L_) ush[t] = g_U[b * L_ + t];
    for (int idx = t; idx < E_ * 2; idx += 256) {
        int e = idx >> 1, p = 50 + (idx & 1);
        g_ATTNP[(size_t)b * E_ * 52 + e * 52 + p] = make_float2(0.f, 0.f);
    }
    __syncthreads();
    for (int e = w; e < E_; e += 8) {
        const float4* er = (const float4*)(g_EDGE + ((size_t)b * E_ + e) * D_);
        float d = 0.f;
        #pragma unroll
        for (int i = 0; i < 4; i++) {
            float4 ev = er[lane + 32 * i];
            float4 wv = wsh[lane + 32 * i];
            d += ev.x * wv.x + ev.y * wv.y + ev.z * wv.z + ev.w * wv.w;
        }
        for (int off = 16; off; off >>= 1) d += __shfl_xor_sync(0xffffffffu, d, off);
        if (lane == 0) vsh[e] = d;
    }
    __syncthreads();

    if (t < L_) {
        int l = t;
        float u = ush[l];
        float vals[E_];
        float mx = -3.4e38f;
        #pragma unroll
        for (int e = 0; e < E_; e++) {
            float s2 = leaky(u + vsh[e]);
            float val = (HT[((size_t)b * E_ + e) * L_ + l] > 0) ? s2 : NEGF;
            vals[e] = val;
            mx = fmaxf(mx, val);
        }
        float sum = 0.f;
        #pragma unroll
        for (int e = 0; e < E_; e++) { vals[e] = expf(vals[e] - mx); sum += vals[e]; }
        float inv = 1.f / sum;
        float* op = (float*)(g_ATTNP + (size_t)b * E_ * 52);
        #pragma unroll
        for (int e = 0; e < E_; e++) op[(e * 52 + (l >> 1)) * 2 + (l & 1)] = vals[e] * inv;
    }
}

// ---- K5: node = att_node @ edge + x; write out twice.
//      grid (B,4), block 416 = 13 warps x 4 l-pairs (proven R4 tile).
__global__ void __launch_bounds__(416, 2) k5(const int* __restrict__ inputs,
                                             const float* __restrict__ emb1,
                                             float* __restrict__ out) {
    int b = blockIdx.x;
    int dt = blockIdx.y * DT;
    __shared__ float es[E_][DT];          // 25.6 KB
    __shared__ float2 anp[E_][52];        // 20.8 KB
    __shared__ int sidx[L_];
    int t = threadIdx.x;

    if (t < L_) sidx[t] = inputs[b * L_ + t];
    for (int idx = t; idx < E_ * (DT / 4); idx += 416) {
        int e = idx >> 5, q = idx & 31;
        ((float4*)es[e])[q] = *(const float4*)(g_EDGE + ((size_t)b * E_ + e) * D_ + dt + q * 4);
    }
    {
        const float4* src = (const float4*)(g_ATTNP + (size_t)b * E_ * 52);
        float4* dst = (float4*)&anp[0][0];
        for (int idx = t; idx < E_ * 52 / 2; idx += 416) dst[idx] = src[idx];
    }
    __syncthreads();

    int lane = t & 31, w = t >> 5;   // w 0..12
    int j0 = lane * 4;
    int p0 = 4 * w;                  // pairs p0..p0+3
    ull acc[4][4];
    #pragma unroll
    for (int k = 0; k < 4; k++)
        #pragma unroll
        for (int j = 0; j < 4; j++) acc[k][j] = 0ULL;

    #pragma unroll 2
    for (int e = 0; e < E_; e++) {
        float4 xv = *(const float4*)&es[e][j0];
        ull xx[4] = {dup2(xv.x), dup2(xv.y), dup2(xv.z), dup2(xv.w)};
        ulonglong2 wa = *(const ulonglong2*)&anp[e][p0];
        ulonglong2 wb = *(const ulonglong2*)&anp[e][p0 + 2];
        #pragma unroll
        for (int j = 0; j < 4; j++) {
            acc[0][j] = fma2(wa.x, xx[j], acc[0][j]);
            acc[1][j] = fma2(wa.y, xx[j], acc[1][j]);
            acc[2][j] = fma2(wb.x, xx[j], acc[2][j]);
            acc[3][j] = fma2(wb.y, xx[j], acc[3][j]);
        }
    }
    #pragma unroll
    for (int k = 0; k < 4; k++) {
        int p = p0 + k;
        if (p < 50) {
            int l0 = 2 * p;
            size_t off0 = ((size_t)b * L_ + l0) * D_ + dt + j0;
            size_t off1 = off0 + D_;
            const float* x0p = emb1 + (size_t)sidx[l0] * D_ + dt + j0;
            const float* x1p = emb1 + (size_t)sidx[l0 + 1] * D_ + dt + j0;
            float4 x0 = *(const float4*)x0p;
            float4 x1 = *(const float4*)x1p;
            float4 o0 = make_float4(lo32(acc[k][0]) + x0.x, lo32(acc[k][1]) + x0.y,
                                    lo32(acc[k][2]) + x0.z, lo32(acc[k][3]) + x0.w);
            float4 o1 = make_float4(hi32(acc[k][0]) + x1.x, hi32(acc[k][1]) + x1.y,
                                    hi32(acc[k][2]) + x1.z, hi32(acc[k][3]) + x1.w);
            *(float4*)(out + off0) = o0;
            *(float4*)(out + BLD + off0) = o0;
            *(float4*)(out + off1) = o1;
            *(float4*)(out + BLD + off1) = o1;
        }
    }
}

extern "C" void kernel_launch(void* const* d_in, const int* in_sizes, int n_in,
                              void* d_out, int out_size) {
    const int*   inputs = (const int*)d_in[0];
    const int*   HT     = (const int*)d_in[1];
    const float* emb1   = (const float*)d_in[4];
    const float* emb2   = (const float*)d_in[5];
    const float* W2     = (const float*)d_in[6];
    const float* W3     = (const float*)d_in[7];
    const float* ctx    = (const float*)d_in[8];
    const float* a      = (const float*)d_in[9];
    const float* a2     = (const float*)d_in[10];
    float* out = (float*)d_out;

    k0<<<4, 512>>>(W2, W3, ctx, a, a2);
    k1<<<B_ * L_, 128>>>(inputs, emb1, emb2, out + 2 * BLD);
    k2<<<B_, 256>>>(HT);
    k3<<<dim3(B_, 4), 448>>>(inputs, emb1);
    k4<<<B_, 256>>>(HT);
    k5<<<dim3(B_, 4), 416>>>(inputs, emb1, out);
}